// round 12
// baseline (speedup 1.0000x reference)
#include <cuda_runtime.h>
#include <cuda_bf16.h>

#define BATCH 2
#define NPTS  65536
#define KNN   16
#define DCH   32

#define CBLOCKS 2048   // compute-role blocks: one thread per (b, n, k-quad)
#define FBLOCKS 4096   // feat-role blocks: one thread per (b, 4-channels, n)

// Single launch, block-role partitioned: blocks [0, CBLOCKS) compute the
// conv+BN+ReLU half with the R4-winning schedule; blocks [CBLOCKS, ...) do
// the feature broadcast with 4 independent loads/thread (MLP=4). Both halves
// run co-resident so their store streams interleave at the DRAM controller.
__global__ __launch_bounds__(256) void lse_kernel(
    const float* __restrict__ coords,    // (B, N, 3)
    const float* __restrict__ features,  // (B, D, N, 1)
    const int*   __restrict__ idx,       // (B, N, K)
    const float* __restrict__ w,         // (D, 10)
    const float* __restrict__ bias,      // (D,)
    const float* __restrict__ gamma,
    const float* __restrict__ beta,
    const float* __restrict__ mean,
    const float* __restrict__ var,
    float* __restrict__ out)             // (B, 2D, N, K)
{
    const size_t cstride = (size_t)NPTS * KNN;   // per-channel stride in out
    int t = threadIdx.x;

    if (blockIdx.x >= CBLOCKS) {
        // ---------------- feature-broadcast role ----------------
        // thread -> (b, channel-quad c4, n); 4 independent loads, 16 stores.
        int gid = (blockIdx.x - CBLOCKS) * blockDim.x + t;  // over B*(D/4)*N
        int n  = gid & (NPTS - 1);
        int c4 = (gid >> 16) & (DCH / 4 - 1);
        int b  = gid >> 19;

        const float* fb = features + (size_t)b * DCH * NPTS + (size_t)n;
        int c0 = c4 * 4;
        float f0 = __ldg(fb + (size_t)(c0 + 0) * NPTS);
        float f1 = __ldg(fb + (size_t)(c0 + 1) * NPTS);
        float f2 = __ldg(fb + (size_t)(c0 + 2) * NPTS);
        float f3 = __ldg(fb + (size_t)(c0 + 3) * NPTS);

        size_t base = ((size_t)b * 2 * DCH + DCH + c0) * cstride
                      + (size_t)n * KNN;
        float fv[4] = {f0, f1, f2, f3};
#pragma unroll
        for (int i = 0; i < 4; i++) {
            float4 v = make_float4(fv[i], fv[i], fv[i], fv[i]);
            float4* p = reinterpret_cast<float4*>(out + base + (size_t)i * cstride);
            __stcs(p + 0, v);
            __stcs(p + 1, v);
            __stcs(p + 2, v);
            __stcs(p + 3, v);
        }
        return;
    }

    // ---------------- compute role (R4-winning schedule) ----------------
    __shared__ float4 s_wa[DCH];  // we.x, we.y, we.z, wn.x
    __shared__ float4 s_wb[DCH];  // wn.y, wn.z, wd,   bias'
    if (t < DCH) {
        float sc = gamma[t] * rsqrtf(var[t] + 1e-5f);
        const float* wr = w + t * 10;
        float w0 = wr[0], w1 = wr[1], w2 = wr[2], w3 = wr[3], w4 = wr[4];
        float w5 = wr[5], w6 = wr[6], w7 = wr[7], w8 = wr[8], w9 = wr[9];
        s_wa[t] = make_float4((w0 + w6) * sc, (w1 + w7) * sc, (w2 + w8) * sc,
                              (w3 - w6) * sc);
        s_wb[t] = make_float4((w4 - w7) * sc, (w5 - w8) * sc, w9 * sc,
                              (bias[t] - mean[t]) * sc + beta[t]);
    }
    __syncthreads();

    int gid = blockIdx.x * blockDim.x + t;       // 0 .. B*N*4 - 1
    int kq  = gid & 3;                           // which quad of k
    int n   = (gid >> 2) & (NPTS - 1);
    int b   = gid >> 18;                         // gid / (4*N)

    const float* cb = coords + (size_t)b * NPTS * 3;
    float cx = cb[(size_t)n * 3 + 0];
    float cy = cb[(size_t)n * 3 + 1];
    float cz = cb[(size_t)n * 3 + 2];

    int4 ii = *reinterpret_cast<const int4*>(
        idx + ((size_t)b * NPTS + (size_t)n) * KNN + kq * 4);

    float nx[4], ny[4], nz[4], dist[4];
#pragma unroll
    for (int j = 0; j < 4; j++) {
        int id = (&ii.x)[j];
        float x = __ldg(cb + (size_t)id * 3 + 0);
        float y = __ldg(cb + (size_t)id * 3 + 1);
        float z = __ldg(cb + (size_t)id * 3 + 2);
        nx[j] = x; ny[j] = y; nz[j] = z;
        float ddx = cx - x, ddy = cy - y, ddz = cz - z;
        dist[j] = sqrtf(ddx * ddx + ddy * ddy + ddz * ddz);
    }

    size_t out_base = (size_t)b * 2 * DCH * cstride + (size_t)n * KNN
                      + (size_t)kq * 4;

#pragma unroll
    for (int o = 0; o < DCH; o++) {
        float4 wa = s_wa[o];
        float4 wb = s_wb[o];
        float base = wb.w + wa.x * cx + wa.y * cy + wa.z * cz;
        float4 r;
        float* rp = &r.x;
#pragma unroll
        for (int j = 0; j < 4; j++) {
            float v = base + wa.w * nx[j] + wb.x * ny[j] + wb.y * nz[j]
                           + wb.z * dist[j];
            rp[j] = fmaxf(v, 0.0f);
        }
        __stcs(reinterpret_cast<float4*>(out + out_base + (size_t)o * cstride),
               r);
    }
}

extern "C" void kernel_launch(void* const* d_in, const int* in_sizes, int n_in,
                              void* d_out, int out_size) {
    const float* coords   = (const float*)d_in[0];
    const float* features = (const float*)d_in[1];
    const int*   idx      = (const int*)d_in[2];
    const float* w        = (const float*)d_in[3];
    const float* bias     = (const float*)d_in[4];
    const float* gamma    = (const float*)d_in[5];
    const float* beta     = (const float*)d_in[6];
    const float* mean     = (const float*)d_in[7];
    const float* var      = (const float*)d_in[8];
    float* out = (float*)d_out;

    lse_kernel<<<CBLOCKS + FBLOCKS, 256>>>(coords, features, idx, w, bias,
                                           gamma, beta, mean, var, out);
}

// round 13
// speedup vs baseline: 1.2029x; 1.2029x over previous
#include <cuda_runtime.h>
#include <cuda_bf16.h>

#define BATCH 2
#define NPTS  65536
#define KNN   16
#define DCH   32

// Champion kernel (R4). One thread handles (b, n, quad-of-4 k's). All 64
// output channels for that (n, k-quad) are written as float4 streaming
// stores (evict-first): the output is write-once, never re-read, and the
// stcs policy lets L2 coalesce dirty sectors without churning the cache.
// BN is folded into the conv; the 10-channel concat is folded to 7 FMAs:
// dot(w, [ext, nb, ext-nb, dist]) = (w0:3 + w6:9)·ext + (w3:6 - w6:9)·nb + w9*dist
__global__ __launch_bounds__(256) void lse_kernel(
    const float* __restrict__ coords,    // (B, N, 3)
    const float* __restrict__ features,  // (B, D, N, 1)
    const int*   __restrict__ idx,       // (B, N, K)
    const float* __restrict__ w,         // (D, 10)
    const float* __restrict__ bias,      // (D,)
    const float* __restrict__ gamma,
    const float* __restrict__ beta,
    const float* __restrict__ mean,
    const float* __restrict__ var,
    float* __restrict__ out)             // (B, 2D, N, K)
{
    __shared__ float4 s_wa[DCH];  // we.x, we.y, we.z, wn.x
    __shared__ float4 s_wb[DCH];  // wn.y, wn.z, wd,   bias'
    int t = threadIdx.x;
    if (t < DCH) {
        float sc = gamma[t] * rsqrtf(var[t] + 1e-5f);
        const float* wr = w + t * 10;
        float w0 = wr[0], w1 = wr[1], w2 = wr[2], w3 = wr[3], w4 = wr[4];
        float w5 = wr[5], w6 = wr[6], w7 = wr[7], w8 = wr[8], w9 = wr[9];
        s_wa[t] = make_float4((w0 + w6) * sc, (w1 + w7) * sc, (w2 + w8) * sc,
                              (w3 - w6) * sc);
        s_wb[t] = make_float4((w4 - w7) * sc, (w5 - w8) * sc, w9 * sc,
                              (bias[t] - mean[t]) * sc + beta[t]);
    }
    __syncthreads();

    int gid = blockIdx.x * blockDim.x + t;       // 0 .. B*N*4 - 1
    int kq  = gid & 3;                           // which quad of k
    int n   = (gid >> 2) & (NPTS - 1);
    int b   = gid >> 18;                         // gid / (4*N)

    const float* cb = coords + (size_t)b * NPTS * 3;
    float cx = cb[(size_t)n * 3 + 0];
    float cy = cb[(size_t)n * 3 + 1];
    float cz = cb[(size_t)n * 3 + 2];

    int4 ii = *reinterpret_cast<const int4*>(
        idx + ((size_t)b * NPTS + (size_t)n) * KNN + kq * 4);

    float nx[4], ny[4], nz[4], dist[4];
#pragma unroll
    for (int j = 0; j < 4; j++) {
        int id = (&ii.x)[j];
        float x = __ldg(cb + (size_t)id * 3 + 0);
        float y = __ldg(cb + (size_t)id * 3 + 1);
        float z = __ldg(cb + (size_t)id * 3 + 2);
        nx[j] = x; ny[j] = y; nz[j] = z;
        float ddx = cx - x, ddy = cy - y, ddz = cz - z;
        dist[j] = sqrtf(ddx * ddx + ddy * ddy + ddz * ddz);
    }

    const size_t cstride = (size_t)NPTS * KNN;   // per-channel stride in out
    size_t out_base = (size_t)b * 2 * DCH * cstride + (size_t)n * KNN
                      + (size_t)kq * 4;

    // Computed half: y = relu(conv+BN)
#pragma unroll
    for (int o = 0; o < DCH; o++) {
        float4 wa = s_wa[o];
        float4 wb = s_wb[o];
        float base = wb.w + wa.x * cx + wa.y * cy + wa.z * cz;
        float4 r;
        float* rp = &r.x;
#pragma unroll
        for (int j = 0; j < 4; j++) {
            float v = base + wa.w * nx[j] + wb.x * ny[j] + wb.y * nz[j]
                           + wb.z * dist[j];
            rp[j] = fmaxf(v, 0.0f);
        }
        __stcs(reinterpret_cast<float4*>(out + out_base + (size_t)o * cstride),
               r);
    }

    // Broadcast half: features replicated across K
    const float* fb = features + (size_t)b * DCH * NPTS + (size_t)n;
    size_t fout = out_base + (size_t)DCH * cstride;
#pragma unroll
    for (int c = 0; c < DCH; c++) {
        float f = __ldg(fb + (size_t)c * NPTS);
        __stcs(reinterpret_cast<float4*>(out + fout + (size_t)c * cstride),
               make_float4(f, f, f, f));
    }
}

extern "C" void kernel_launch(void* const* d_in, const int* in_sizes, int n_in,
                              void* d_out, int out_size) {
    const float* coords   = (const float*)d_in[0];
    const float* features = (const float*)d_in[1];
    const int*   idx      = (const int*)d_in[2];
    const float* w        = (const float*)d_in[3];
    const float* bias     = (const float*)d_in[4];
    const float* gamma    = (const float*)d_in[5];
    const float* beta     = (const float*)d_in[6];
    const float* mean     = (const float*)d_in[7];
    const float* var      = (const float*)d_in[8];
    float* out = (float*)d_out;

    const int total   = BATCH * NPTS * 4;   // one thread per (b, n, k-quad)
    const int threads = 256;
    const int blocks  = total / threads;    // 2048
    lse_kernel<<<blocks, threads>>>(coords, features, idx, w, bias,
                                    gamma, beta, mean, var, out);
}